// round 8
// baseline (speedup 1.0000x reference)
#include <cuda_runtime.h>
#include <cstdint>

#define HIN 512
#define WIN 512
#define NP  724
#define NA  180
#define PAD 106
#define CENTER 361.5f
#define PI_D 3.14159265358979323846
#define PSTR 528     // row stride in float2 (4224 B = 33 x 128 B, line-aligned rows)
#define PROWS 516    // rows rj = 0..515

// Padded pair buffers. Layout: buf[(j+2)*PSTR + (i+2)] = (a(j,i), a(j+1,i))
//   g_pN: a(j,i) = img[j][i]   (shallow angles: i = image col, j = image row)
//   g_pT: a(j,i) = img[i][j]   (steep angles:   i = image row, j = image col)
// Data rows rj=2..513 (j in [0,511]); row rj=1 is the j=-1 half-pair (0, a(0,i));
// rows 0,514,515 and cols 0,1,514..527 are never written -> stay zero forever,
// so clamping (i,j) to [-2,513] makes every fully-OOB sample read exact zeros.
__device__ float2 g_pN[PROWS * PSTR];
__device__ float2 g_pT[PROWS * PSTR];

__global__ __launch_bounds__(256) void prep_kernel(const float* __restrict__ img) {
    __shared__ float tile[33][34];
    const int bx = blockIdx.x * 32;
    const int by = blockIdx.y * 32;
    // load 33x33 halo tile (zero outside image)
    for (int idx = threadIdx.x; idx < 33 * 33; idx += 256) {
        const int r = idx / 33, cc = idx % 33;
        const int gy = by + r, gx = bx + cc;
        float val = 0.f;
        if (gy < HIN && gx < WIN) val = img[gy * WIN + gx];
        tile[r][cc] = val;
    }
    __syncthreads();
    const int tx = threadIdx.x & 31;
    const int tg = threadIdx.x >> 5;   // 0..7
#pragma unroll
    for (int r = tg; r < 32; r += 8)
        g_pN[(size_t)(by + r + 2) * PSTR + (bx + tx + 2)] =
            make_float2(tile[r][tx], tile[r + 1][tx]);
#pragma unroll
    for (int cc = tg; cc < 32; cc += 8)
        g_pT[(size_t)(bx + cc + 2) * PSTR + (by + tx + 2)] =
            make_float2(tile[tx][cc], tile[tx][cc + 1]);
    // j = -1 rows (rj = 1): pair = (0, first in-image value along the pair dim)
    if (by == 0 && tg == 0)
        g_pN[PSTR + (bx + tx + 2)] = make_float2(0.f, tile[0][tx]);
    if (bx == 0 && tg == 1)
        g_pT[PSTR + (by + tx + 2)] = make_float2(0.f, tile[tx][0]);
}

template <bool STEEP>
__global__ __launch_bounds__(256) void radon_kernel(
    float* __restrict__ sino,        // [180,724]
    float* __restrict__ rot)         // [180,724,724]
{
    const int y = blockIdx.x;   // output row within rotated frame
    // steep angles (|s|>|c|) are exactly n in [45,134]
    const int n = STEEP ? (int)blockIdx.y + 45
                        : ((int)blockIdx.y < 45 ? (int)blockIdx.y : (int)blockIdx.y + 90);
    const int t = threadIdx.x;

    float s, c;
    sincosf((float)n * (float)(PI_D / 179.0), &s, &c);

    const float v = (float)y - CENTER;
    const float ixr = fmaf(-s, v, CENTER);
    const float iyr = fmaf( c, v, CENTER);

    const float2* __restrict__ buf = STEEP ? g_pT : g_pN;
    float* __restrict__ rowOut = rot + ((size_t)n * NP + y) * NP;

    const float u0 = (float)t - CENTER;
    float ix = fmaf(c, u0, ixr);
    float iy = fmaf(s, u0, iyr);
    const float dix = 256.0f * c;
    const float diy = 256.0f * s;

    float sum = 0.0f;

#pragma unroll
    for (int k = 0; k < 3; k++) {
        const int x = t + k * 256;
        if (k < 2 || x < NP) {
            const float xf = floorf(ix);
            const float yf = floorf(iy);
            const float wx = ix - xf;
            const float wy = iy - yf;
            const int x0 = (int)xf - PAD;   // input-image coords
            const int y0 = (int)yf - PAD;

            // i = warp-compact dim, j = pair dim (compile-time role swap)
            int i = STEEP ? y0 : x0;
            int j = STEEP ? x0 : y0;
            const float wi = STEEP ? wy : wx;
            const float wj = STEEP ? wx : wy;
            // clamp into the zero-bordered frame: any fully-OOB sample reads zeros
            i = min(max(i, -2), 513);
            j = min(max(j, -2), 513);

            const float2* p = buf + (size_t)(j + 2) * PSTR + (i + 2);
            const float2 v0 = __ldg(p);       // (a(j,i),   a(j+1,i))
            const float2 v1 = __ldg(p + 1);   // (a(j,i+1), a(j+1,i+1))

            const float top = fmaf(wi, v1.x - v0.x, v0.x);
            const float bot = fmaf(wi, v1.y - v0.y, v0.y);
            const float r   = fmaf(wj, bot - top, top);
            rowOut[x] = r;
            sum += r;
        }
        ix += dix;
        iy += diy;
    }

    // block reduction of row sum -> sinogram[n, y]
#pragma unroll
    for (int o = 16; o > 0; o >>= 1)
        sum += __shfl_down_sync(0xffffffffu, sum, o);
    __shared__ float ws[8];
    if ((t & 31) == 0) ws[t >> 5] = sum;
    __syncthreads();
    if (t == 0) {
        float tot = 0.f;
#pragma unroll
        for (int i = 0; i < 8; i++) tot += ws[i];
        sino[(size_t)n * NP + y] = tot;
    }
}

extern "C" void kernel_launch(void* const* d_in, const int* in_sizes, int n_in,
                              void* d_out, int out_size) {
    const float* x = (const float*)d_in[0];
    float* sino = (float*)d_out;                 // [180,724]
    float* rot  = sino + (size_t)NA * NP;        // [180,1,724,724]

    prep_kernel<<<dim3(WIN / 32, HIN / 32), 256>>>(x);
    dim3 grid(NP, 90);
    radon_kernel<false><<<grid, 256>>>(sino, rot);
    radon_kernel<true ><<<grid, 256>>>(sino, rot);
}

// round 9
// speedup vs baseline: 1.2695x; 1.2695x over previous
#include <cuda_runtime.h>
#include <cstdint>

#define HIN 512
#define WIN 512
#define NP  724
#define NA  180
#define PAD 106
#define CENTER 361.5f
#define PI_D 3.14159265358979323846
#define PSTR 528     // row stride in float2 (4224 B = 33 x 128 B, line-aligned rows)
#define PROWS 516    // rows rj = 0..515

// Padded pair buffers. Layout: buf[rj*PSTR + ci] with rj=j+2, ci=i+2:
//   buf[.] = (a(j,i), a(j+1,i))
//   g_pN: a(j,i) = img[j][i]   (shallow: i = image col, j = image row)
//   g_pT: a(j,i) = img[i][j]   (steep:   i = image row, j = image col)
// Data rows rj=2..513; row rj=1 is the j=-1 half-pair (0, a(0,i)); col ci=1 is
// the i=-1 zero pair whose right neighbor (ci=2) supplies a(j,0).
__device__ float2 g_pN[PROWS * PSTR];
__device__ float2 g_pT[PROWS * PSTR];

__global__ __launch_bounds__(256) void prep_kernel(const float* __restrict__ img) {
    __shared__ float tile[33][34];
    const int bx = blockIdx.x * 32;
    const int by = blockIdx.y * 32;
    // load 33x33 halo tile (zero outside image)
    for (int idx = threadIdx.x; idx < 33 * 33; idx += 256) {
        const int r = idx / 33, cc = idx % 33;
        const int gy = by + r, gx = bx + cc;
        float val = 0.f;
        if (gy < HIN && gx < WIN) val = img[gy * WIN + gx];
        tile[r][cc] = val;
    }
    __syncthreads();
    const int tx = threadIdx.x & 31;
    const int tg = threadIdx.x >> 5;   // 0..7
#pragma unroll
    for (int r = tg; r < 32; r += 8)
        g_pN[(size_t)(by + r + 2) * PSTR + (bx + tx + 2)] =
            make_float2(tile[r][tx], tile[r + 1][tx]);
#pragma unroll
    for (int cc = tg; cc < 32; cc += 8)
        g_pT[(size_t)(bx + cc + 2) * PSTR + (by + tx + 2)] =
            make_float2(tile[tx][cc], tile[tx][cc + 1]);
    // j = -1 rows (rj = 1): pair = (0, first in-image value along the pair dim)
    if (by == 0 && tg == 0)
        g_pN[PSTR + (bx + tx + 2)] = make_float2(0.f, tile[0][tx]);
    if (bx == 0 && tg == 1)
        g_pT[PSTR + (by + tx + 2)] = make_float2(0.f, tile[tx][0]);
}

template <bool STEEP>
__global__ __launch_bounds__(256) void radon_kernel(
    float* __restrict__ sino,        // [180,724]
    float* __restrict__ rot)         // [180,724,724]
{
    const int y = blockIdx.x;   // output row within rotated frame
    // steep angles (|s|>|c|) are exactly n in [45,134]
    const int n = STEEP ? (int)blockIdx.y + 45
                        : ((int)blockIdx.y < 45 ? (int)blockIdx.y : (int)blockIdx.y + 90);
    const int t = threadIdx.x;

    float s, c;
    sincosf((float)n * (float)(PI_D / 179.0), &s, &c);

    const float v = (float)y - CENTER;
    // fold (-PAD + 2) = -104 into the offsets: coords land directly in buffer space
    const float B = CENTER - 104.0f;
    const float ixr = fmaf(-s, v, B);
    const float iyr = fmaf( c, v, B);

    const float2* __restrict__ buf = STEEP ? g_pT : g_pN;
    float* __restrict__ rowOut = rot + ((size_t)n * NP + y) * NP;

    const float u0 = (float)t - CENTER;
    float ixb = fmaf(c, u0, ixr);   // buffer-space x coord
    float iyb = fmaf(s, u0, iyr);   // buffer-space y coord
    const float dix = 256.0f * c;
    const float diy = 256.0f * s;

    float sum = 0.0f;

#pragma unroll
    for (int k = 0; k < 3; k++) {
        const int x = t + k * 256;
        if (k < 2 || x < NP) {
            const float xf = floorf(ixb);
            const float yf = floorf(iyb);
            const float wx = ixb - xf;
            const float wy = iyb - yf;
            const int cx = (int)xf;
            const int cy = (int)yf;

            // i = warp-compact dim, j = pair dim (compile-time role swap)
            const int   ci = STEEP ? cy : cx;
            const int   rj = STEEP ? cx : cy;
            const float wi = STEEP ? wy : wx;
            const float wj = STEEP ? wx : wy;

            // 2x2 neighborhood overlaps the image iff ci,rj in [1,513]
            const unsigned inside =
                ((unsigned)(ci - 1) < 513u) & ((unsigned)(rj - 1) < 513u);

            float2 v0 = make_float2(0.f, 0.f);
            float2 v1 = make_float2(0.f, 0.f);
            const float2* p = buf + (size_t)rj * PSTR + ci;
            asm volatile(
                "{\n\t"
                ".reg .pred p0;\n\t"
                "setp.ne.u32 p0, %4, 0;\n\t"
                "@p0 ld.global.nc.v2.f32 {%0, %1}, [%5];\n\t"
                "@p0 ld.global.nc.v2.f32 {%2, %3}, [%5+8];\n\t"
                "}"
                : "+f"(v0.x), "+f"(v0.y), "+f"(v1.x), "+f"(v1.y)
                : "r"(inside), "l"(p));

            const float top = fmaf(wi, v1.x - v0.x, v0.x);
            const float bot = fmaf(wi, v1.y - v0.y, v0.y);
            const float r   = fmaf(wj, bot - top, top);
            rowOut[x] = r;
            sum += r;
        }
        ixb += dix;
        iyb += diy;
    }

    // block reduction of row sum -> sinogram[n, y]
#pragma unroll
    for (int o = 16; o > 0; o >>= 1)
        sum += __shfl_down_sync(0xffffffffu, sum, o);
    __shared__ float ws[8];
    if ((t & 31) == 0) ws[t >> 5] = sum;
    __syncthreads();
    if (t == 0) {
        float tot = 0.f;
#pragma unroll
        for (int i = 0; i < 8; i++) tot += ws[i];
        sino[(size_t)n * NP + y] = tot;
    }
}

extern "C" void kernel_launch(void* const* d_in, const int* in_sizes, int n_in,
                              void* d_out, int out_size) {
    const float* x = (const float*)d_in[0];
    float* sino = (float*)d_out;                 // [180,724]
    float* rot  = sino + (size_t)NA * NP;        // [180,1,724,724]

    prep_kernel<<<dim3(WIN / 32, HIN / 32), 256>>>(x);
    dim3 grid(NP, 90);
    radon_kernel<false><<<grid, 256>>>(sino, rot);
    radon_kernel<true ><<<grid, 256>>>(sino, rot);
}

// round 12
// speedup vs baseline: 1.3598x; 1.0711x over previous
#include <cuda_runtime.h>
#include <cstdint>

#define HIN 512
#define WIN 512
#define NP  724
#define NA  180
#define PAD 106
#define CENTER 361.5f
#define PI_D 3.14159265358979323846
#define QSTR 520     // row stride in float4 (8320 B = 65 x 128 B)
#define QROWS 514    // rows rj = 0..513 used; loads restricted to [1,513]

// Quad buffers: buf[(j+2)*QSTR + (i+2)] = (A, C, B, D) for cell (j,i):
//   A=a(j,i)  C=a(j+1,i)  B=a(j,i+1)  D=a(j+1,i+1)
//   g_qN: a(j,i) = img[j][i]   (shallow: i = image col, j = image row)
//   g_qT: a(j,i) = img[i][j]   (steep:   i = image row, j = image col)
// prep_kernel writes every cell with j,i in [-1,511] each replay (halo-padded,
// so border quads contain the correct zeros). Loads only touch rj,ci in [1,513].
__device__ float4 g_qN[QROWS * QSTR];
__device__ float4 g_qT[QROWS * QSTR];

__global__ __launch_bounds__(256) void prep_kernel(const float* __restrict__ img) {
    __shared__ float tile[34][36];
    const int bx = blockIdx.x * 32;
    const int by = blockIdx.y * 32;
    // halo tile: tile[r][c] = img[by-1+r][bx-1+c], zero outside the image
    for (int idx = threadIdx.x; idx < 34 * 34; idx += 256) {
        const int r = idx / 34, c = idx % 34;
        const int gy = by - 1 + r, gx = bx - 1 + c;
        float v = 0.f;
        if ((unsigned)gy < (unsigned)HIN && (unsigned)gx < (unsigned)WIN)
            v = img[gy * WIN + gx];
        tile[r][c] = v;
    }
    __syncthreads();
    // normal quads: cell (j,i) = (by-1+r, bx-1+c); consecutive idx -> consecutive i
    for (int idx = threadIdx.x; idx < 33 * 33; idx += 256) {
        const int r = idx / 33, c = idx % 33;
        g_qN[(size_t)(by + 1 + r) * QSTR + (bx + 1 + c)] =
            make_float4(tile[r][c], tile[r + 1][c], tile[r][c + 1], tile[r + 1][c + 1]);
    }
    // transposed quads: j = bx-1+c, i = by-1+r; consecutive idx -> consecutive i (=r)
    for (int idx = threadIdx.x; idx < 33 * 33; idx += 256) {
        const int c = idx / 33, r = idx % 33;
        g_qT[(size_t)(bx + 1 + c) * QSTR + (by + 1 + r)] =
            make_float4(tile[r][c], tile[r][c + 1], tile[r + 1][c], tile[r + 1][c + 1]);
    }
}

template <bool STEEP>
__global__ __launch_bounds__(256) void radon_kernel(
    float* __restrict__ sino,        // [180,724]
    float* __restrict__ rot)         // [180,724,724]
{
    const int y = blockIdx.x;   // output row within rotated frame
    // steep angles (|s|>|c|) are exactly n in [45,134]
    const int n = STEEP ? (int)blockIdx.y + 45
                        : ((int)blockIdx.y < 45 ? (int)blockIdx.y : (int)blockIdx.y + 90);
    const int t = threadIdx.x;

    float s, c;
    sincosf((float)n * (float)(PI_D / 179.0), &s, &c);

    const float v = (float)y - CENTER;
    // fold (-PAD + 2) = -104 into the offsets: coords land directly in buffer space
    const float B0 = CENTER - 104.0f;
    const float ixr = fmaf(-s, v, B0);
    const float iyr = fmaf( c, v, B0);

    const float4* __restrict__ buf = STEEP ? g_qT : g_qN;
    float* __restrict__ rowOut = rot + ((size_t)n * NP + y) * NP;

    const float u0 = (float)t - CENTER;
    float ixb = fmaf(c, u0, ixr);   // buffer-space x coord
    float iyb = fmaf(s, u0, iyr);   // buffer-space y coord
    const float dix = 256.0f * c;
    const float diy = 256.0f * s;

    float sum = 0.0f;

#pragma unroll
    for (int k = 0; k < 3; k++) {
        const int x = t + k * 256;
        if (k < 2 || x < NP) {
            const float xf = floorf(ixb);
            const float yf = floorf(iyb);
            const float wx = ixb - xf;
            const float wy = iyb - yf;
            const int cx = (int)xf;
            const int cy = (int)yf;

            // i = warp-compact dim, j = pair dim (compile-time role swap)
            const int   ci = STEEP ? cy : cx;
            const int   rj = STEEP ? cx : cy;
            const float wi = STEEP ? wy : wx;
            const float wj = STEEP ? wx : wy;

            // 2x2 neighborhood overlaps the image iff ci,rj in [1,513]
            const unsigned inside =
                ((unsigned)(ci - 1) < 513u) & ((unsigned)(rj - 1) < 513u);

            float4 q = make_float4(0.f, 0.f, 0.f, 0.f);
            const float4* p = buf + (size_t)rj * QSTR + ci;
            asm volatile(
                "{\n\t"
                ".reg .pred p0;\n\t"
                "setp.ne.u32 p0, %4, 0;\n\t"
                "@p0 ld.global.nc.v4.f32 {%0, %1, %2, %3}, [%5];\n\t"
                "}"
                : "+f"(q.x), "+f"(q.y), "+f"(q.z), "+f"(q.w)
                : "r"(inside), "l"(p));

            // q = (A, C, B, D)
            const float top = fmaf(wi, q.z - q.x, q.x);
            const float bot = fmaf(wi, q.w - q.y, q.y);
            const float r   = fmaf(wj, bot - top, top);
            rowOut[x] = r;
            sum += r;
        }
        ixb += dix;
        iyb += diy;
    }

    // block reduction of row sum -> sinogram[n, y]
#pragma unroll
    for (int o = 16; o > 0; o >>= 1)
        sum += __shfl_down_sync(0xffffffffu, sum, o);
    __shared__ float ws[8];
    if ((t & 31) == 0) ws[t >> 5] = sum;
    __syncthreads();
    if (t == 0) {
        float tot = 0.f;
#pragma unroll
        for (int i = 0; i < 8; i++) tot += ws[i];
        sino[(size_t)n * NP + y] = tot;
    }
}

extern "C" void kernel_launch(void* const* d_in, const int* in_sizes, int n_in,
                              void* d_out, int out_size) {
    const float* x = (const float*)d_in[0];
    float* sino = (float*)d_out;                 // [180,724]
    float* rot  = sino + (size_t)NA * NP;        // [180,1,724,724]

    prep_kernel<<<dim3(WIN / 32, HIN / 32), 256>>>(x);
    dim3 grid(NP, 90);
    radon_kernel<false><<<grid, 256>>>(sino, rot);
    radon_kernel<true ><<<grid, 256>>>(sino, rot);
}